// round 2
// baseline (speedup 1.0000x reference)
#include <cuda_runtime.h>
#include <cuda_bf16.h>
#include <math.h>

#define NB 4
#define NC 512
#define NG 2048
#define CHN 3
#define NP 3
#define KB 10
#define NGB (NB*NG)          // 8192
#define PLANE (NB*NG)        // 8192 per (c,p) plane
#define OUTC 64

// output region offsets (floats), tuple concat order:
// y_out (4,2048,64) | n_f (4,2048,9) | fourier_prior (4,2048,3,3) | n_h1 (4,2048,3,3) | h0_f (4,2048,9)
#define OFF_YOUT 0
#define OFF_NF   (NGB*OUTC)            // 524288
#define OFF_FP   (OFF_NF  + NGB*9)     // 598016
#define OFF_NH1  (OFF_FP  + NGB*9)     // 671744
#define OFF_H0   (OFF_NH1 + NGB*9)     // 745472

// scratch (no allocations allowed -> device globals)
__device__ float g_nh1pos[9 * PLANE];   // planar [cp][b*NG+g]
__device__ float g_convout[9 * PLANE];  // planar
__device__ float g_bnscale[9];
__device__ float g_bnshift[9];

__device__ __forceinline__ float ex2(float x) {
    float r;
    asm("ex2.approx.ftz.f32 %0, %1;" : "=f"(r) : "f"(x));
    return r;
}

// ---------------------------------------------------------------------------
// Kernel A: RBF h0/h1 (segmented over nc) + Fourier prior + n_h1 / n_h1_pos
// grid: 256 blocks (b*64 + gtile), block: 128 threads = 4 seg x 32 g
// ---------------------------------------------------------------------------
__global__ __launch_bounds__(128) void kA(
    const float* __restrict__ x_c, const float* __restrict__ y_c,
    const float* __restrict__ x_g, const float* __restrict__ sigma,
    const float* __restrict__ mu, const float* __restrict__ eps1,
    const float* __restrict__ b_u, const float* __restrict__ rw,
    float* __restrict__ out)
{
    __shared__ float xs[NC][CHN];
    __shared__ float ys[NC][CHN];
    __shared__ float xgs[32][CHN];
    __shared__ float sws[KB][NP];
    __shared__ float sbs[KB][NP];
    __shared__ float rws[KB];
    __shared__ float red0[4][32][9];
    __shared__ float red1[4][32][9];

    const int b   = blockIdx.x >> 6;
    const int gt  = blockIdx.x & 63;
    const int tid = threadIdx.x;
    const int seg = tid >> 5;
    const int gl  = tid & 31;

    const float* xcb = x_c + b * NC * CHN;
    const float* ycb = y_c + b * NC * CHN;
    for (int i = tid; i < NC * CHN; i += 128) {
        ((float*)xs)[i] = xcb[i];
        ((float*)ys)[i] = ycb[i];
    }
    const float* xgb = x_g + b * NG * CHN;
    for (int i = tid; i < 32 * CHN; i += 128)
        ((float*)xgs)[i] = xgb[gt * 32 * CHN + i];

    if (tid < KB * NP) {
        int k = tid / NP, p = tid % NP;
        float inv = 1.0f / (expf(sigma[p]) + 1e-6f);
        sws[k][p] = expf(mu[p]) + inv * eps1[(b * KB + k) * NP + p];
        sbs[k][p] = 6.283185307179586f * b_u[(b * KB + k) * NP + p];
    }
    if (tid < KB) rws[tid] = rw[tid];

    // al_p = -0.5/(exp(sigma_p)+eps)^2 * log2(e)
    float s0 = expf(sigma[0]) + 1e-6f;
    float s1v = expf(sigma[1]) + 1e-6f;
    float s2v = expf(sigma[2]) + 1e-6f;
    const float L2E = 1.4426950408889634f;
    float al0 = -0.5f / (s0 * s0) * L2E;
    float al1 = -0.5f / (s1v * s1v) * L2E;
    float al2 = -0.5f / (s2v * s2v) * L2E;

    __syncthreads();

    float xg0 = xgs[gl][0], xg1 = xgs[gl][1], xg2 = xgs[gl][2];
    float h0a[9], h1a[9];
#pragma unroll
    for (int j = 0; j < 9; j++) { h0a[j] = 0.0f; h1a[j] = 0.0f; }

    const int n0 = seg * 128;
#pragma unroll 4
    for (int n = n0; n < n0 + 128; ++n) {
        float x0 = xs[n][0], x1 = xs[n][1], x2 = xs[n][2];
        float yv0 = ys[n][0], yv1 = ys[n][1], yv2 = ys[n][2];
        float d, t, w;
        d = x0 - xg0; t = d * d;
        w = ex2(al0 * t); h0a[0] += w; h1a[0] += w * yv0;
        w = ex2(al1 * t); h0a[1] += w; h1a[1] += w * yv0;
        w = ex2(al2 * t); h0a[2] += w; h1a[2] += w * yv0;
        d = x1 - xg1; t = d * d;
        w = ex2(al0 * t); h0a[3] += w; h1a[3] += w * yv1;
        w = ex2(al1 * t); h0a[4] += w; h1a[4] += w * yv1;
        w = ex2(al2 * t); h0a[5] += w; h1a[5] += w * yv1;
        d = x2 - xg2; t = d * d;
        w = ex2(al0 * t); h0a[6] += w; h1a[6] += w * yv2;
        w = ex2(al1 * t); h0a[7] += w; h1a[7] += w * yv2;
        w = ex2(al2 * t); h0a[8] += w; h1a[8] += w * yv2;
    }

#pragma unroll
    for (int j = 0; j < 9; j++) { red0[seg][gl][j] = h0a[j]; red1[seg][gl][j] = h1a[j]; }
    __syncthreads();

    // epilogue: 288 items (g_local, c, p)
    const int base = b * NG + gt * 32;
    for (int item = tid; item < 288; item += 128) {
        int gg = item / 9;
        int cp = item % 9;
        int c = cp / 3, p = cp % 3;
        float h0 = red0[0][gg][cp] + red0[1][gg][cp] + red0[2][gg][cp] + red0[3][gg][cp];
        float h1 = red1[0][gg][cp] + red1[1][gg][cp] + red1[2][gg][cp] + red1[3][gg][cp];
        float nh1 = h1 / (h0 + 1e-6f);
        float xgv = xgs[gg][c];
        float fp = 0.0f;
#pragma unroll
        for (int k = 0; k < KB; k++)
            fp += rws[k] * cosf(sws[k][p] * xgv + sbs[k][p]);
        fp *= 0.4472135954999579f;   // sqrt(2/10)
        int gi = base + gg;
        int o9 = gi * 9 + cp;
        out[OFF_H0 + o9]  = h0;
        out[OFF_NH1 + o9] = nh1;
        out[OFF_FP + o9]  = fp;
        g_nh1pos[cp * PLANE + gi] = nh1 + fp;
    }
}

// ---------------------------------------------------------------------------
// Kernel C: depthwise conv1d per (c,p), planar layout, zero padding per batch
// ---------------------------------------------------------------------------
__global__ __launch_bounds__(256) void kC(
    const float* __restrict__ cw1, const float* __restrict__ cb1,
    const float* __restrict__ cw2, const float* __restrict__ cb2,
    const float* __restrict__ cw3, const float* __restrict__ cb3)
{
    int i = blockIdx.x * blockDim.x + threadIdx.x;
    if (i >= NGB) return;
    int g = i & (NG - 1);

#pragma unroll
    for (int c = 0; c < 3; c++) {
        // p = 0 : ksz 3, pad 1
        {
            const float* pl = g_nh1pos + (c * 3 + 0) * PLANE;
            float acc = cb1[c];
#pragma unroll
            for (int t = 0; t < 3; t++) {
                int gg = g - 1 + t;
                if (gg >= 0 && gg < NG) acc += cw1[c * 3 + t] * pl[i - 1 + t];
            }
            g_convout[(c * 3 + 0) * PLANE + i] = acc;
        }
        // p = 1 : ksz 5, pad 2
        {
            const float* pl = g_nh1pos + (c * 3 + 1) * PLANE;
            float acc = cb2[c];
#pragma unroll
            for (int t = 0; t < 5; t++) {
                int gg = g - 2 + t;
                if (gg >= 0 && gg < NG) acc += cw2[c * 5 + t] * pl[i - 2 + t];
            }
            g_convout[(c * 3 + 1) * PLANE + i] = acc;
        }
        // p = 2 : ksz 9, pad 4
        {
            const float* pl = g_nh1pos + (c * 3 + 2) * PLANE;
            float acc = cb3[c];
#pragma unroll
            for (int t = 0; t < 9; t++) {
                int gg = g - 4 + t;
                if (gg >= 0 && gg < NG) acc += cw3[c * 9 + t] * pl[i - 4 + t];
            }
            g_convout[(c * 3 + 2) * PLANE + i] = acc;
        }
    }
}

// ---------------------------------------------------------------------------
// Kernel S: BN stats per (c,p) plane -> scale/shift. Deterministic tree reduce.
// grid: 9 blocks x 256 threads
// ---------------------------------------------------------------------------
__global__ __launch_bounds__(256) void kS(
    const float* __restrict__ bn_gamma, const float* __restrict__ bn_beta)
{
    __shared__ float sa[256];
    __shared__ float sq[256];
    int cp = blockIdx.x;
    int c = cp / 3, p = cp % 3;
    const float* pl = g_convout + cp * PLANE;
    int tid = threadIdx.x;
    float a = 0.0f, q = 0.0f;
    for (int i = tid; i < PLANE; i += 256) {
        float v = pl[i];
        a += v; q += v * v;
    }
    sa[tid] = a; sq[tid] = q;
    __syncthreads();
    for (int s = 128; s > 0; s >>= 1) {
        if (tid < s) { sa[tid] += sa[tid + s]; sq[tid] += sq[tid + s]; }
        __syncthreads();
    }
    if (tid == 0) {
        float inv_n = 1.0f / (float)PLANE;
        float mean = sa[0] * inv_n;
        float var = sq[0] * inv_n - mean * mean;
        float sc = bn_gamma[p * 3 + c] * rsqrtf(var + 1e-5f);
        g_bnscale[cp] = sc;
        g_bnshift[cp] = bn_beta[p * 3 + c] - mean * sc;
    }
}

// ---------------------------------------------------------------------------
// Kernel D: BN affine -> n_f, then feat=[h0_f, n_f] @ g_w^T + g_b -> y_out
// grid: 32 blocks x 256 threads (one thread per (b,g))
// ---------------------------------------------------------------------------
__global__ __launch_bounds__(256) void kD(
    const float* __restrict__ gw, const float* __restrict__ gb,
    float* __restrict__ out)
{
    __shared__ float sgw[OUTC * 18];
    __shared__ float sgb[OUTC];
    __shared__ float ssc[9], ssh[9];
    int tid = threadIdx.x;
    for (int i = tid; i < OUTC * 18; i += 256) sgw[i] = gw[i];
    if (tid < OUTC) sgb[tid] = gb[tid];
    if (tid < 9) { ssc[tid] = g_bnscale[tid]; ssh[tid] = g_bnshift[tid]; }
    __syncthreads();

    int i = blockIdx.x * 256 + tid;
    if (i >= NGB) return;

    float feat[18];
#pragma unroll
    for (int j = 0; j < 9; j++) feat[j] = out[OFF_H0 + i * 9 + j];
#pragma unroll
    for (int j = 0; j < 9; j++) {
        float v = g_convout[j * PLANE + i] * ssc[j] + ssh[j];
        feat[9 + j] = v;
        out[OFF_NF + i * 9 + j] = v;
    }

    float4* yo = (float4*)(out + OFF_YOUT + (size_t)i * OUTC);
#pragma unroll
    for (int o4 = 0; o4 < OUTC / 4; o4++) {
        float4 r;
        float acc0 = sgb[o4 * 4 + 0], acc1 = sgb[o4 * 4 + 1];
        float acc2 = sgb[o4 * 4 + 2], acc3 = sgb[o4 * 4 + 3];
#pragma unroll
        for (int j = 0; j < 18; j++) {
            float f = feat[j];
            acc0 += sgw[(o4 * 4 + 0) * 18 + j] * f;
            acc1 += sgw[(o4 * 4 + 1) * 18 + j] * f;
            acc2 += sgw[(o4 * 4 + 2) * 18 + j] * f;
            acc3 += sgw[(o4 * 4 + 3) * 18 + j] * f;
        }
        r.x = acc0; r.y = acc1; r.z = acc2; r.w = acc3;
        yo[o4] = r;
    }
}

// ---------------------------------------------------------------------------
extern "C" void kernel_launch(void* const* d_in, const int* in_sizes, int n_in,
                              void* d_out, int out_size)
{
    const float* x_c     = (const float*)d_in[0];
    const float* y_c     = (const float*)d_in[1];
    const float* x_g     = (const float*)d_in[2];
    const float* sigma   = (const float*)d_in[3];
    const float* mu      = (const float*)d_in[4];
    const float* eps1    = (const float*)d_in[5];
    const float* b_u     = (const float*)d_in[6];
    const float* rw      = (const float*)d_in[7];
    const float* cw1     = (const float*)d_in[8];
    const float* cb1     = (const float*)d_in[9];
    const float* cw2     = (const float*)d_in[10];
    const float* cb2     = (const float*)d_in[11];
    const float* cw3     = (const float*)d_in[12];
    const float* cb3     = (const float*)d_in[13];
    const float* bn_g    = (const float*)d_in[14];
    const float* bn_b    = (const float*)d_in[15];
    const float* g_w     = (const float*)d_in[16];
    const float* g_b     = (const float*)d_in[17];
    float* out = (float*)d_out;

    kA<<<NB * (NG / 32), 128>>>(x_c, y_c, x_g, sigma, mu, eps1, b_u, rw, out);
    kC<<<(NGB + 255) / 256, 256>>>(cw1, cb1, cw2, cb2, cw3, cb3);
    kS<<<9, 256>>>(bn_g, bn_b);
    kD<<<(NGB + 255) / 256, 256>>>(g_w, g_b, out);
}

// round 3
// speedup vs baseline: 1.0130x; 1.0130x over previous
#include <cuda_runtime.h>
#include <cuda_bf16.h>
#include <math.h>

#define NB 4
#define NC 512
#define NG 2048
#define CHN 3
#define NP 3
#define KB 10
#define NGB (NB*NG)          // 8192
#define PLANE (NB*NG)        // 8192 per (c,p) plane
#define OUTC 64

// output region offsets (floats), tuple concat order:
// y_out (4,2048,64) | n_f (4,2048,9) | fourier_prior (4,2048,3,3) | n_h1 (4,2048,3,3) | h0_f (4,2048,9)
#define OFF_YOUT 0
#define OFF_NF   (NGB*OUTC)            // 524288
#define OFF_FP   (OFF_NF  + NGB*9)     // 598016
#define OFF_NH1  (OFF_FP  + NGB*9)     // 671744
#define OFF_H0   (OFF_NH1 + NGB*9)     // 745472

// scratch (no allocations allowed -> device globals)
__device__ float g_nh1pos[9 * PLANE];   // planar [cp][b*NG+g]
__device__ float g_convout[9 * PLANE];  // planar
__device__ float g_bnscale[9];
__device__ float g_bnshift[9];

__device__ __forceinline__ float ex2(float x) {
    float r;
    asm("ex2.approx.ftz.f32 %0, %1;" : "=f"(r) : "f"(x));
    return r;
}

// ---------------------------------------------------------------------------
// Kernel A: RBF h0/h1 (segmented over nc) + Fourier prior + n_h1 / n_h1_pos
// grid: 256 blocks (b*64 + gtile), block: 128 threads = 4 seg x 32 g
// ---------------------------------------------------------------------------
__global__ __launch_bounds__(128) void kA(
    const float* __restrict__ x_c, const float* __restrict__ y_c,
    const float* __restrict__ x_g, const float* __restrict__ sigma,
    const float* __restrict__ mu, const float* __restrict__ eps1,
    const float* __restrict__ b_u, const float* __restrict__ rw,
    float* __restrict__ out)
{
    __shared__ float xs[NC][CHN];
    __shared__ float ys[NC][CHN];
    __shared__ float xgs[32][CHN];
    __shared__ float sws[KB][NP];
    __shared__ float sbs[KB][NP];
    __shared__ float rws[KB];
    __shared__ float red0[4][32][9];
    __shared__ float red1[4][32][9];

    const int b   = blockIdx.x >> 6;
    const int gt  = blockIdx.x & 63;
    const int tid = threadIdx.x;
    const int seg = tid >> 5;
    const int gl  = tid & 31;

    const float* xcb = x_c + b * NC * CHN;
    const float* ycb = y_c + b * NC * CHN;
    for (int i = tid; i < NC * CHN; i += 128) {
        ((float*)xs)[i] = xcb[i];
        ((float*)ys)[i] = ycb[i];
    }
    const float* xgb = x_g + b * NG * CHN;
    for (int i = tid; i < 32 * CHN; i += 128)
        ((float*)xgs)[i] = xgb[gt * 32 * CHN + i];

    if (tid < KB * NP) {
        int k = tid / NP, p = tid % NP;
        float inv = 1.0f / (expf(sigma[p]) + 1e-6f);
        sws[k][p] = expf(mu[p]) + inv * eps1[(b * KB + k) * NP + p];
        sbs[k][p] = 6.283185307179586f * b_u[(b * KB + k) * NP + p];
    }
    if (tid < KB) rws[tid] = rw[tid];

    // al_p = -0.5/(exp(sigma_p)+eps)^2 * log2(e)
    float s0 = expf(sigma[0]) + 1e-6f;
    float s1v = expf(sigma[1]) + 1e-6f;
    float s2v = expf(sigma[2]) + 1e-6f;
    const float L2E = 1.4426950408889634f;
    float al0 = -0.5f / (s0 * s0) * L2E;
    float al1 = -0.5f / (s1v * s1v) * L2E;
    float al2 = -0.5f / (s2v * s2v) * L2E;

    __syncthreads();

    float xg0 = xgs[gl][0], xg1 = xgs[gl][1], xg2 = xgs[gl][2];
    float h0a[9], h1a[9];
#pragma unroll
    for (int j = 0; j < 9; j++) { h0a[j] = 0.0f; h1a[j] = 0.0f; }

    const int n0 = seg * 128;
#pragma unroll 4
    for (int n = n0; n < n0 + 128; ++n) {
        float x0 = xs[n][0], x1 = xs[n][1], x2 = xs[n][2];
        float yv0 = ys[n][0], yv1 = ys[n][1], yv2 = ys[n][2];
        float d, t, w;
        d = x0 - xg0; t = d * d;
        w = ex2(al0 * t); h0a[0] += w; h1a[0] += w * yv0;
        w = ex2(al1 * t); h0a[1] += w; h1a[1] += w * yv0;
        w = ex2(al2 * t); h0a[2] += w; h1a[2] += w * yv0;
        d = x1 - xg1; t = d * d;
        w = ex2(al0 * t); h0a[3] += w; h1a[3] += w * yv1;
        w = ex2(al1 * t); h0a[4] += w; h1a[4] += w * yv1;
        w = ex2(al2 * t); h0a[5] += w; h1a[5] += w * yv1;
        d = x2 - xg2; t = d * d;
        w = ex2(al0 * t); h0a[6] += w; h1a[6] += w * yv2;
        w = ex2(al1 * t); h0a[7] += w; h1a[7] += w * yv2;
        w = ex2(al2 * t); h0a[8] += w; h1a[8] += w * yv2;
    }

#pragma unroll
    for (int j = 0; j < 9; j++) { red0[seg][gl][j] = h0a[j]; red1[seg][gl][j] = h1a[j]; }
    __syncthreads();

    // epilogue: 288 items (g_local, c, p)
    const int base = b * NG + gt * 32;
    for (int item = tid; item < 288; item += 128) {
        int gg = item / 9;
        int cp = item % 9;
        int c = cp / 3, p = cp % 3;
        float h0 = red0[0][gg][cp] + red0[1][gg][cp] + red0[2][gg][cp] + red0[3][gg][cp];
        float h1 = red1[0][gg][cp] + red1[1][gg][cp] + red1[2][gg][cp] + red1[3][gg][cp];
        float nh1 = h1 / (h0 + 1e-6f);
        float xgv = xgs[gg][c];
        float fp = 0.0f;
#pragma unroll
        for (int k = 0; k < KB; k++)
            fp += rws[k] * cosf(sws[k][p] * xgv + sbs[k][p]);
        fp *= 0.4472135954999579f;   // sqrt(2/10)
        int gi = base + gg;
        int o9 = gi * 9 + cp;
        out[OFF_H0 + o9]  = h0;
        out[OFF_NH1 + o9] = nh1;
        out[OFF_FP + o9]  = fp;
        g_nh1pos[cp * PLANE + gi] = nh1 + fp;
    }
}

// ---------------------------------------------------------------------------
// Kernel C: depthwise conv1d per (c,p), planar layout, zero padding per batch
// ---------------------------------------------------------------------------
__global__ __launch_bounds__(256) void kC(
    const float* __restrict__ cw1, const float* __restrict__ cb1,
    const float* __restrict__ cw2, const float* __restrict__ cb2,
    const float* __restrict__ cw3, const float* __restrict__ cb3)
{
    int i = blockIdx.x * blockDim.x + threadIdx.x;
    if (i >= NGB) return;
    int g = i & (NG - 1);

#pragma unroll
    for (int c = 0; c < 3; c++) {
        // p = 0 : ksz 3, pad 1
        {
            const float* pl = g_nh1pos + (c * 3 + 0) * PLANE;
            float acc = cb1[c];
#pragma unroll
            for (int t = 0; t < 3; t++) {
                int gg = g - 1 + t;
                if (gg >= 0 && gg < NG) acc += cw1[c * 3 + t] * pl[i - 1 + t];
            }
            g_convout[(c * 3 + 0) * PLANE + i] = acc;
        }
        // p = 1 : ksz 5, pad 2
        {
            const float* pl = g_nh1pos + (c * 3 + 1) * PLANE;
            float acc = cb2[c];
#pragma unroll
            for (int t = 0; t < 5; t++) {
                int gg = g - 2 + t;
                if (gg >= 0 && gg < NG) acc += cw2[c * 5 + t] * pl[i - 2 + t];
            }
            g_convout[(c * 3 + 1) * PLANE + i] = acc;
        }
        // p = 2 : ksz 9, pad 4
        {
            const float* pl = g_nh1pos + (c * 3 + 2) * PLANE;
            float acc = cb3[c];
#pragma unroll
            for (int t = 0; t < 9; t++) {
                int gg = g - 4 + t;
                if (gg >= 0 && gg < NG) acc += cw3[c * 9 + t] * pl[i - 4 + t];
            }
            g_convout[(c * 3 + 2) * PLANE + i] = acc;
        }
    }
}

// ---------------------------------------------------------------------------
// Kernel S: BN stats per (c,p) plane -> scale/shift. Deterministic tree reduce.
// grid: 9 blocks x 256 threads
// ---------------------------------------------------------------------------
__global__ __launch_bounds__(256) void kS(
    const float* __restrict__ bn_gamma, const float* __restrict__ bn_beta)
{
    __shared__ float sa[256];
    __shared__ float sq[256];
    int cp = blockIdx.x;
    int c = cp / 3, p = cp % 3;
    const float* pl = g_convout + cp * PLANE;
    int tid = threadIdx.x;
    float a = 0.0f, q = 0.0f;
    for (int i = tid; i < PLANE; i += 256) {
        float v = pl[i];
        a += v; q += v * v;
    }
    sa[tid] = a; sq[tid] = q;
    __syncthreads();
    for (int s = 128; s > 0; s >>= 1) {
        if (tid < s) { sa[tid] += sa[tid + s]; sq[tid] += sq[tid + s]; }
        __syncthreads();
    }
    if (tid == 0) {
        float inv_n = 1.0f / (float)PLANE;
        float mean = sa[0] * inv_n;
        float var = sq[0] * inv_n - mean * mean;
        float sc = bn_gamma[p * 3 + c] * rsqrtf(var + 1e-5f);
        g_bnscale[cp] = sc;
        g_bnshift[cp] = bn_beta[p * 3 + c] - mean * sc;
    }
}

// ---------------------------------------------------------------------------
// Kernel D: BN affine -> n_f, then feat=[h0_f, n_f] @ g_w^T + g_b -> y_out
// grid: 32 blocks x 256 threads (one thread per (b,g))
// ---------------------------------------------------------------------------
__global__ __launch_bounds__(256) void kD(
    const float* __restrict__ gw, const float* __restrict__ gb,
    float* __restrict__ out)
{
    __shared__ float sgw[OUTC * 18];
    __shared__ float sgb[OUTC];
    __shared__ float ssc[9], ssh[9];
    int tid = threadIdx.x;
    for (int i = tid; i < OUTC * 18; i += 256) sgw[i] = gw[i];
    if (tid < OUTC) sgb[tid] = gb[tid];
    if (tid < 9) { ssc[tid] = g_bnscale[tid]; ssh[tid] = g_bnshift[tid]; }
    __syncthreads();

    int i = blockIdx.x * 256 + tid;
    if (i >= NGB) return;

    float feat[18];
#pragma unroll
    for (int j = 0; j < 9; j++) feat[j] = out[OFF_H0 + i * 9 + j];
#pragma unroll
    for (int j = 0; j < 9; j++) {
        float v = g_convout[j * PLANE + i] * ssc[j] + ssh[j];
        feat[9 + j] = v;
        out[OFF_NF + i * 9 + j] = v;
    }

    float4* yo = (float4*)(out + OFF_YOUT + (size_t)i * OUTC);
#pragma unroll
    for (int o4 = 0; o4 < OUTC / 4; o4++) {
        float4 r;
        float acc0 = sgb[o4 * 4 + 0], acc1 = sgb[o4 * 4 + 1];
        float acc2 = sgb[o4 * 4 + 2], acc3 = sgb[o4 * 4 + 3];
#pragma unroll
        for (int j = 0; j < 18; j++) {
            float f = feat[j];
            acc0 += sgw[(o4 * 4 + 0) * 18 + j] * f;
            acc1 += sgw[(o4 * 4 + 1) * 18 + j] * f;
            acc2 += sgw[(o4 * 4 + 2) * 18 + j] * f;
            acc3 += sgw[(o4 * 4 + 3) * 18 + j] * f;
        }
        r.x = acc0; r.y = acc1; r.z = acc2; r.w = acc3;
        yo[o4] = r;
    }
}

// ---------------------------------------------------------------------------
extern "C" void kernel_launch(void* const* d_in, const int* in_sizes, int n_in,
                              void* d_out, int out_size)
{
    const float* x_c     = (const float*)d_in[0];
    const float* y_c     = (const float*)d_in[1];
    const float* x_g     = (const float*)d_in[2];
    const float* sigma   = (const float*)d_in[3];
    const float* mu      = (const float*)d_in[4];
    const float* eps1    = (const float*)d_in[5];
    const float* b_u     = (const float*)d_in[6];
    const float* rw      = (const float*)d_in[7];
    const float* cw1     = (const float*)d_in[8];
    const float* cb1     = (const float*)d_in[9];
    const float* cw2     = (const float*)d_in[10];
    const float* cb2     = (const float*)d_in[11];
    const float* cw3     = (const float*)d_in[12];
    const float* cb3     = (const float*)d_in[13];
    const float* bn_g    = (const float*)d_in[14];
    const float* bn_b    = (const float*)d_in[15];
    const float* g_w     = (const float*)d_in[16];
    const float* g_b     = (const float*)d_in[17];
    float* out = (float*)d_out;

    kA<<<NB * (NG / 32), 128>>>(x_c, y_c, x_g, sigma, mu, eps1, b_u, rw, out);
    kC<<<(NGB + 255) / 256, 256>>>(cw1, cb1, cw2, cb2, cw3, cb3);
    kS<<<9, 256>>>(bn_g, bn_b);
    kD<<<(NGB + 255) / 256, 256>>>(g_w, g_b, out);
}